// round 5
// baseline (speedup 1.0000x reference)
#include <cuda_runtime.h>
#include <cuda_fp16.h>
#include <cstdint>
#include <cstddef>

#define NROWS 8192
#define CDIM  128
#define NCTA  296          // 2 per SM on 148 SMs
#define NGEMM 256          // GEMM CTAs (32-row tiles)
#define NHELP 40           // helper CTAs
#define CHUNK 2048
#define NCHUNK 4

// ---------------- device scratch ----------------
__device__ float  g_dinv[NROWS];                 // D^-1/2
__device__ __half g_zT_h[CDIM * NROWS];          // zT[c][j] fp16 (B operand)
__device__ float  g_z[NROWS * CDIM];             // z[j][c] fp32 (self-loop term)
__device__ int    g_cnt[8];                      // [0..3]=deg chunk, [4..7]=zt chunk

// ---------------- helpers ----------------
__device__ __forceinline__ uint32_t smem_u32(const void* p) {
    uint32_t a;
    asm("{ .reg .u64 t; cvta.to.shared.u64 t, %1; cvt.u32.u64 %0, t; }" : "=r"(a) : "l"(p));
    return a;
}
__device__ __forceinline__ uint32_t pack_f16x2(float x, float y) {
    uint32_t h;
    asm("cvt.rn.f16x2.f32 %0, %1, %2;" : "=r"(h) : "f"(y), "f"(x));
    return h;
}
#define CP_ASYNC16(dst, src) \
    asm volatile("cp.async.cg.shared.global [%0], [%1], 16;" :: "r"(dst), "l"(src) : "memory")
#define CP_COMMIT() asm volatile("cp.async.commit_group;" ::: "memory")
#define CP_WAIT0()  asm volatile("cp.async.wait_group 0;" ::: "memory")

#define LDMATRIX_X4(r0, r1, r2, r3, addr)                                    \
    asm volatile("ldmatrix.sync.aligned.m8n8.x4.shared.b16 {%0,%1,%2,%3}, [%4];" \
                 : "=r"(r0), "=r"(r1), "=r"(r2), "=r"(r3) : "r"(addr))

__device__ __forceinline__ void mma_f16(float& d0, float& d1, float& d2, float& d3,
                                        uint32_t a0, uint32_t a1, uint32_t a2, uint32_t a3,
                                        uint32_t b0, uint32_t b1) {
    asm volatile(
        "mma.sync.aligned.m16n8k16.row.col.f32.f16.f16.f32 "
        "{%0,%1,%2,%3}, {%4,%5,%6,%7}, {%8,%9}, {%0,%1,%2,%3};"
        : "+f"(d0), "+f"(d1), "+f"(d2), "+f"(d3)
        : "r"(a0), "r"(a1), "r"(a2), "r"(a3), "r"(b0), "r"(b1));
}

__device__ __forceinline__ void arrive(int idx) {
    __threadfence();
    atomicAdd(&g_cnt[idx], 1);
}
__device__ __forceinline__ void cta_wait(int idx, int target, int tid) {
    if (tid == 0) {
        volatile int* c = g_cnt;
        while (c[idx] != target) __nanosleep(128);
    }
    __syncthreads();
    __threadfence();
}

// ---------------- smem layout (dynamic, 25600 B) ----------------
static constexpr int RSTRIDE = 80;
static constexpr int A_TILE = 32 * RSTRIDE;        // 2560
static constexpr int B_TILE = 128 * RSTRIDE;       // 10240
static constexpr int OFF_A0 = 0;
static constexpr int OFF_A1 = A_TILE;
static constexpr int OFF_B0 = 2 * A_TILE;
static constexpr int OFF_B1 = 2 * A_TILE + B_TILE;
static constexpr int SMEM_DYN = 2 * A_TILE + 2 * B_TILE;  // 25600

// ============================================================================
// phase: deg -> g_dinv for chunk s (rows strided over P participants)
// ============================================================================
__device__ void deg_work(const float* __restrict__ adj, int s, int pidx, int P, int tid) {
    __shared__ float ws[8];
    for (int jj = pidx; jj < CHUNK; jj += P) {
        const int row = s * CHUNK + jj;
        const float4* p = reinterpret_cast<const float4*>(adj + (size_t)row * NROWS);
        float sum = 0.0f;
        #pragma unroll 8
        for (int i = tid; i < NROWS / 4; i += 256) {
            float4 v = p[i];
            sum += (v.x + v.y) + (v.z + v.w);
        }
        #pragma unroll
        for (int o = 16; o > 0; o >>= 1) sum += __shfl_xor_sync(0xFFFFFFFFu, sum, o);
        if ((tid & 31) == 0) ws[tid >> 5] = sum;
        __syncthreads();
        if (tid == 0) {
            float t = 0.0f;
            #pragma unroll
            for (int i = 0; i < 8; i++) t += ws[i];
            g_dinv[row] = rsqrtf(t + 1.0f);
        }
        __syncthreads();
    }
}

// ============================================================================
// phase: z (fp32) + zT (fp16) for chunk s; groups of 16 rows
// ============================================================================
__device__ void zt_work(const float* __restrict__ x, const float* __restrict__ W,
                        float* xs, int s, int pidx, int P, int tid) {
    const int c = tid & 127;
    const int half = tid >> 7;
    for (int g = pidx; g < CHUNK / 16; g += P) {
        const int j0 = s * CHUNK + g * 16;
        __syncthreads();
        for (int idx = tid; idx < 16 * 128; idx += 256)
            xs[idx] = x[(size_t)(j0 + (idx >> 7)) * 128 + (idx & 127)];
        __syncthreads();
        float acc[8];
        #pragma unroll
        for (int r = 0; r < 8; r++) acc[r] = 0.0f;
        for (int k = 0; k < 128; k += 4) {
            const float4 wv = __ldg(reinterpret_cast<const float4*>(W + c * 128 + k));
            #pragma unroll
            for (int r = 0; r < 8; r++) {
                const float4 xv = *reinterpret_cast<const float4*>(&xs[(half * 8 + r) * 128 + k]);
                acc[r] += xv.x * wv.x + xv.y * wv.y + xv.z * wv.z + xv.w * wv.w;
            }
        }
        #pragma unroll
        for (int r = 0; r < 8; r++) {
            const int j = j0 + half * 8 + r;
            const float v = g_dinv[j] * acc[r];
            g_z[(size_t)j * 128 + c] = v;
            g_zT_h[(size_t)c * NROWS + j] = __float2half_rn(v);
        }
    }
}

// ============================================================================
// main persistent kernel
// ============================================================================
__global__ void __launch_bounds__(256, 2) kmain(const float* __restrict__ x,
                                                const float* __restrict__ adj,
                                                const float* __restrict__ W,
                                                const float* __restrict__ bias,
                                                float* __restrict__ out) {
    extern __shared__ char smem[];
    const uint32_t base = smem_u32(smem);
    const int cta = blockIdx.x;
    const int tid = threadIdx.x;

    // ---------- chunk 0: all 296 CTAs ----------
    deg_work(adj, 0, cta, NCTA, tid);
    if (tid == 0) arrive(0);
    cta_wait(0, NCTA, tid);
    zt_work(x, W, reinterpret_cast<float*>(smem), 0, cta, NCTA, tid);
    if (tid == 0) arrive(4);

    if (cta >= NGEMM) {
        // ---------- helpers: chunks 1..3 ----------
        const int pidx = cta - NGEMM;
        for (int s = 1; s < NCHUNK; s++) {
            deg_work(adj, s, pidx, NHELP, tid);
            if (tid == 0) arrive(s);
            cta_wait(s, NHELP, tid);
            zt_work(x, W, reinterpret_cast<float*>(smem), s, pidx, NHELP, tid);
            if (tid == 0) arrive(4 + s);
        }
        return;
    }

    // ---------- GEMM CTA: 32-row tile, full K, chunk-ordered ----------
    const int m0 = cta * 32;
    const int wid = tid >> 5, lane = tid & 31;
    const int gid = lane >> 2, tig = lane & 3;
    const int wm = wid & 1;          // 2 row groups x 16
    const int wn = wid >> 1;         // 4 col groups x 32

    const uint32_t Ab0 = base + OFF_A0, Ab1 = base + OFF_A1;
    const uint32_t Bb0 = base + OFF_B0, Bb1 = base + OFF_B1;

    const int ar = tid >> 3;         // A row 0..31
    const int aqf = tid & 7;         // float4 slot in 32-wide k
    const size_t a_row_off = (size_t)(m0 + ar) * NROWS + aqf * 4;

    float acc[4][4];
    #pragma unroll
    for (int i = 0; i < 4; i++)
        #pragma unroll
        for (int j = 0; j < 4; j++) acc[i][j] = 0.0f;

    float4 pf;
    for (int s = 0; s < NCHUNK; s++) {
        cta_wait(4 + s, s == 0 ? NCTA : NHELP, tid);
        const int kbase = s * CHUNK;

        // prologue for this chunk
        pf = *reinterpret_cast<const float4*>(adj + a_row_off + kbase);
        #pragma unroll
        for (int i = 0; i < 2; i++) {
            const int id = tid + 256 * i;
            const int r = id >> 2, q = id & 3;
            CP_ASYNC16(Bb0 + r * RSTRIDE + q * 16,
                       (const void*)(g_zT_h + (size_t)r * NROWS + kbase + q * 8));
        }
        CP_COMMIT();

        for (int kt = 0; kt < CHUNK / 32; kt++) {
            const uint32_t Ab = (kt & 1) ? Ab1 : Ab0;
            const uint32_t Bb = (kt & 1) ? Bb1 : Bb0;
            // store prefetched A (fp32 -> fp16)
            {
                const uint32_t h0 = pack_f16x2(pf.x, pf.y);
                const uint32_t h1 = pack_f16x2(pf.z, pf.w);
                asm volatile("st.shared.v2.b32 [%0], {%1,%2};"
                             :: "r"(Ab + ar * RSTRIDE + aqf * 8), "r"(h0), "r"(h1)
                             : "memory");
            }
            CP_WAIT0();
            __syncthreads();
            if (kt + 1 < CHUNK / 32) {
                const int k0n = kbase + (kt + 1) * 32;
                pf = *reinterpret_cast<const float4*>(adj + a_row_off + k0n);
                const uint32_t Bn = (kt & 1) ? Bb0 : Bb1;
                #pragma unroll
                for (int i = 0; i < 2; i++) {
                    const int id = tid + 256 * i;
                    const int r = id >> 2, q = id & 3;
                    CP_ASYNC16(Bn + r * RSTRIDE + q * 16,
                               (const void*)(g_zT_h + (size_t)r * NROWS + k0n + q * 8));
                }
            }
            CP_COMMIT();
            // -------- mma --------
            #pragma unroll
            for (int st = 0; st < 2; st++) {
                const int ch = 2 * st + (lane >> 4);
                uint32_t a[4], b[2][4];
                {
                    const int r = wm * 16 + (lane & 15);
                    LDMATRIX_X4(a[0], a[1], a[2], a[3], Ab + r * RSTRIDE + ch * 16);
                }
                #pragma unroll
                for (int p = 0; p < 2; p++) {
                    const int n = wn * 32 + p * 16 + (lane & 15);
                    LDMATRIX_X4(b[p][0], b[p][1], b[p][2], b[p][3],
                                Bb + n * RSTRIDE + ch * 16);
                }
                #pragma unroll
                for (int nt = 0; nt < 4; nt++) {
                    const int p = nt >> 1, sel = nt & 1;
                    mma_f16(acc[nt][0], acc[nt][1], acc[nt][2], acc[nt][3],
                            a[0], a[1], a[2], a[3],
                            b[p][sel], b[p][2 + sel]);
                }
            }
            __syncthreads();
        }
    }

    // ---------- epilogue: out = dinv_i * (acc + z_i) + b ----------
    const int r0 = wm * 16 + gid;
    const int r1 = r0 + 8;
    const float di0 = g_dinv[m0 + r0];
    const float di1 = g_dinv[m0 + r1];
    #pragma unroll
    for (int nt = 0; nt < 4; nt++) {
        const int col = wn * 32 + nt * 8 + tig * 2;
        const float2 bb = *reinterpret_cast<const float2*>(bias + col);
        const float2 z0 = *reinterpret_cast<const float2*>(g_z + (size_t)(m0 + r0) * 128 + col);
        const float2 z1 = *reinterpret_cast<const float2*>(g_z + (size_t)(m0 + r1) * 128 + col);
        float2 o0, o1;
        o0.x = di0 * (acc[nt][0] + z0.x) + bb.x;
        o0.y = di0 * (acc[nt][1] + z0.y) + bb.y;
        o1.x = di1 * (acc[nt][2] + z1.x) + bb.x;
        o1.y = di1 * (acc[nt][3] + z1.y) + bb.y;
        *reinterpret_cast<float2*>(out + (size_t)(m0 + r0) * 128 + col) = o0;
        *reinterpret_cast<float2*>(out + (size_t)(m0 + r1) * 128 + col) = o1;
    }
}

// ============================================================================
// launch
// ============================================================================
extern "C" void kernel_launch(void* const* d_in, const int* in_sizes, int n_in,
                              void* d_out, int out_size) {
    (void)in_sizes; (void)n_in; (void)out_size;
    const float* x   = (const float*)d_in[0];
    const float* adj = (const float*)d_in[1];
    const float* W   = (const float*)d_in[2];
    const float* b   = (const float*)d_in[3];
    float* out = (float*)d_out;

    void* caddr = nullptr;
    cudaGetSymbolAddress(&caddr, g_cnt);
    cudaMemsetAsync(caddr, 0, 8 * sizeof(int));
    kmain<<<NCTA, 256, SMEM_DYN>>>(x, adj, W, b, out);
}

// round 6
// speedup vs baseline: 1.3600x; 1.3600x over previous
#include <cuda_runtime.h>
#include <cuda_fp16.h>
#include <cstdint>
#include <cstddef>

#define NROWS 8192
#define CDIM  128
#define NCTA  296
#define NGEMM 128          // GEMM CTAs: 64 M-tiles x 2 N-halves, full K
#define NHELP (NCTA - NGEMM)
#define CHUNK 2048
#define NCHUNK 4

// ---------------- device scratch ----------------
__device__ float  g_dinv[NROWS];
__device__ __half g_zT_h[CDIM * NROWS];          // zT[c][j] fp16
__device__ float  g_z[NROWS * CDIM];             // z[j][c] fp32
__device__ int    g_cnt[8];                      // [s]=deg chunk s, [4+s]=zt chunk s

// ---------------- helpers ----------------
__device__ __forceinline__ uint32_t smem_u32(const void* p) {
    uint32_t a;
    asm("{ .reg .u64 t; cvta.to.shared.u64 t, %1; cvt.u32.u64 %0, t; }" : "=r"(a) : "l"(p));
    return a;
}
__device__ __forceinline__ uint32_t pack_f16x2(float x, float y) {
    uint32_t h;
    asm("cvt.rn.f16x2.f32 %0, %1, %2;" : "=r"(h) : "f"(y), "f"(x));
    return h;
}
#define CP_ASYNC16(dst, src) \
    asm volatile("cp.async.cg.shared.global [%0], [%1], 16;" :: "r"(dst), "l"(src) : "memory")
#define CP_COMMIT() asm volatile("cp.async.commit_group;" ::: "memory")
#define CP_WAIT0()  asm volatile("cp.async.wait_group 0;" ::: "memory")

#define LDMATRIX_X4(r0, r1, r2, r3, addr)                                    \
    asm volatile("ldmatrix.sync.aligned.m8n8.x4.shared.b16 {%0,%1,%2,%3}, [%4];" \
                 : "=r"(r0), "=r"(r1), "=r"(r2), "=r"(r3) : "r"(addr))

__device__ __forceinline__ void mma_f16(float& d0, float& d1, float& d2, float& d3,
                                        uint32_t a0, uint32_t a1, uint32_t a2, uint32_t a3,
                                        uint32_t b0, uint32_t b1) {
    asm volatile(
        "mma.sync.aligned.m16n8k16.row.col.f32.f16.f16.f32 "
        "{%0,%1,%2,%3}, {%4,%5,%6,%7}, {%8,%9}, {%0,%1,%2,%3};"
        : "+f"(d0), "+f"(d1), "+f"(d2), "+f"(d3)
        : "r"(a0), "r"(a1), "r"(a2), "r"(a3), "r"(b0), "r"(b1));
}

__device__ __forceinline__ void arrive(int idx) {
    __threadfence();
    atomicAdd(&g_cnt[idx], 1);
}
__device__ __forceinline__ void cta_wait(int idx, int target, int tid) {
    if (tid == 0) {
        volatile int* c = g_cnt;
        while (c[idx] < target) __nanosleep(128);
    }
    __syncthreads();
    __threadfence();
}

// ---------------- smem layout ----------------
static constexpr int RSTRIDE = 80;
static constexpr int A_TILE = 128 * RSTRIDE;       // 10240
static constexpr int B_TILE = 64 * RSTRIDE;        // 5120
static constexpr int OFF_A0 = 0;
static constexpr int OFF_A1 = A_TILE;
static constexpr int OFF_B0 = 2 * A_TILE;
static constexpr int OFF_B1 = 2 * A_TILE + B_TILE;
static constexpr int SMEM_DYN = 2 * A_TILE + 2 * B_TILE;  // 30720

// ============================================================================
// deg for chunk s (rows strided over P participants)
// ============================================================================
__device__ void deg_work(const float* __restrict__ adj, int s, int pidx, int P, int tid) {
    __shared__ float ws[8];
    for (int jj = pidx; jj < CHUNK; jj += P) {
        const int row = s * CHUNK + jj;
        const float4* p = reinterpret_cast<const float4*>(adj + (size_t)row * NROWS);
        float sum = 0.0f;
        #pragma unroll 8
        for (int i = tid; i < NROWS / 4; i += 256) {
            float4 v = p[i];
            sum += (v.x + v.y) + (v.z + v.w);
        }
        #pragma unroll
        for (int o = 16; o > 0; o >>= 1) sum += __shfl_xor_sync(0xFFFFFFFFu, sum, o);
        if ((tid & 31) == 0) ws[tid >> 5] = sum;
        __syncthreads();
        if (tid == 0) {
            float t = 0.0f;
            #pragma unroll
            for (int i = 0; i < 8; i++) t += ws[i];
            g_dinv[row] = rsqrtf(t + 1.0f);
        }
        __syncthreads();
    }
}

// ============================================================================
// z (fp32) + zT (fp16) for chunk s; groups of 16 rows strided over P
// ============================================================================
__device__ void zt_work(const float* __restrict__ x, const float* __restrict__ W,
                        float* xs, int s, int pidx, int P, int tid) {
    const int c = tid & 127;
    const int half = tid >> 7;
    for (int g = pidx; g < CHUNK / 16; g += P) {
        const int j0 = s * CHUNK + g * 16;
        __syncthreads();
        for (int idx = tid; idx < 16 * 128; idx += 256)
            xs[idx] = x[(size_t)(j0 + (idx >> 7)) * 128 + (idx & 127)];
        __syncthreads();
        float acc[8];
        #pragma unroll
        for (int r = 0; r < 8; r++) acc[r] = 0.0f;
        for (int k = 0; k < 128; k += 4) {
            const float4 wv = __ldg(reinterpret_cast<const float4*>(W + c * 128 + k));
            #pragma unroll
            for (int r = 0; r < 8; r++) {
                const float4 xv = *reinterpret_cast<const float4*>(&xs[(half * 8 + r) * 128 + k]);
                acc[r] += xv.x * wv.x + xv.y * wv.y + xv.z * wv.z + xv.w * wv.w;
            }
        }
        #pragma unroll
        for (int r = 0; r < 8; r++) {
            const int j = j0 + half * 8 + r;
            const float v = g_dinv[j] * acc[r];
            g_z[(size_t)j * 128 + c] = v;
            g_zT_h[(size_t)c * NROWS + j] = __float2half_rn(v);
        }
    }
}

// ============================================================================
// main persistent kernel
// ============================================================================
__global__ void __launch_bounds__(256, 2) kmain(const float* __restrict__ x,
                                                const float* __restrict__ adj,
                                                const float* __restrict__ W,
                                                const float* __restrict__ bias,
                                                float* __restrict__ out) {
    extern __shared__ char smem[];
    const uint32_t base = smem_u32(smem);
    const int cta = blockIdx.x;
    const int tid = threadIdx.x;

    // ---------- prefix: chunk 0 by all 296 CTAs ----------
    deg_work(adj, 0, cta, NCTA, tid);
    if (tid == 0) arrive(0);
    cta_wait(0, NCTA, tid);
    zt_work(x, W, reinterpret_cast<float*>(smem), 0, cta, NCTA, tid);
    if (tid == 0) arrive(4);

    if (cta >= NGEMM) {
        // ---------- 168 helpers: chunks 1..3 deg + zT ----------
        const int pidx = cta - NGEMM;
        for (int s = 1; s < NCHUNK; s++) {
            deg_work(adj, s, pidx, NHELP, tid);
            if (tid == 0) arrive(s);
            cta_wait(s, NHELP, tid);
            zt_work(x, W, reinterpret_cast<float*>(smem), s, pidx, NHELP, tid);
            if (tid == 0) arrive(4 + s);
        }
        return;
    }

    // ---------- GEMM CTA: 128x64 tile, full K in registers ----------
    const int m0 = (cta >> 1) * 128;
    const int n0 = (cta & 1) * 64;
    const int wid = tid >> 5, lane = tid & 31;
    const int gid = lane >> 2, tig = lane & 3;
    const int wm = wid & 3;          // 4 M groups x 32 rows
    const int wn = wid >> 2;         // 2 N groups x 32 cols

    const uint32_t Ab0 = base + OFF_A0, Ab1 = base + OFF_A1;
    const uint32_t Bb0 = base + OFF_B0, Bb1 = base + OFF_B1;

    // A load slots: 1024 float4 per 128x32 tile -> 4 per thread
    const int ar[4] = { (tid + 0) >> 3, (tid + 256) >> 3, (tid + 512) >> 3, (tid + 768) >> 3 };
    const int aqf = tid & 7;
    // B load slot: 256 16B-chunks per 64x32 tile -> 1 per thread
    const int br = tid >> 2, bq = tid & 3;
    const __half* bsrc_row = g_zT_h + (size_t)(n0 + br) * NROWS + bq * 8;

    float acc[2][4][4];
    #pragma unroll
    for (int i = 0; i < 2; i++)
        #pragma unroll
        for (int j = 0; j < 4; j++)
            #pragma unroll
            for (int t = 0; t < 4; t++) acc[i][j][t] = 0.0f;

    float4 pf[4];
    for (int s = 0; s < NCHUNK; s++) {
        cta_wait(4 + s, s == 0 ? NCTA : NHELP, tid);
        const int kbase = s * CHUNK;

        // chunk prologue
        #pragma unroll
        for (int i = 0; i < 4; i++)
            pf[i] = *reinterpret_cast<const float4*>(
                adj + (size_t)(m0 + ar[i]) * NROWS + kbase + aqf * 4);
        CP_ASYNC16(Bb0 + br * RSTRIDE + bq * 16, (const void*)(bsrc_row + kbase));
        CP_COMMIT();

        for (int kt = 0; kt < CHUNK / 32; kt++) {
            const uint32_t Ab = (kt & 1) ? Ab1 : Ab0;
            const uint32_t Bb = (kt & 1) ? Bb1 : Bb0;
            // store prefetched A (fp32 -> fp16)
            #pragma unroll
            for (int i = 0; i < 4; i++) {
                const uint32_t h0 = pack_f16x2(pf[i].x, pf[i].y);
                const uint32_t h1 = pack_f16x2(pf[i].z, pf[i].w);
                asm volatile("st.shared.v2.b32 [%0], {%1,%2};"
                             :: "r"(Ab + ar[i] * RSTRIDE + aqf * 8), "r"(h0), "r"(h1)
                             : "memory");
            }
            CP_WAIT0();
            __syncthreads();
            if (kt + 1 < CHUNK / 32) {
                const int k0n = kbase + (kt + 1) * 32;
                #pragma unroll
                for (int i = 0; i < 4; i++)
                    pf[i] = *reinterpret_cast<const float4*>(
                        adj + (size_t)(m0 + ar[i]) * NROWS + k0n + aqf * 4);
                CP_ASYNC16(((kt & 1) ? Bb0 : Bb1) + br * RSTRIDE + bq * 16,
                           (const void*)(bsrc_row + k0n));
            }
            CP_COMMIT();
            // -------- mma --------
            #pragma unroll
            for (int st = 0; st < 2; st++) {
                const int ch = 2 * st + (lane >> 4);
                uint32_t a[2][4], b[2][4];
                #pragma unroll
                for (int mt = 0; mt < 2; mt++) {
                    const int r = wm * 32 + mt * 16 + (lane & 15);
                    LDMATRIX_X4(a[mt][0], a[mt][1], a[mt][2], a[mt][3],
                                Ab + r * RSTRIDE + ch * 16);
                }
                #pragma unroll
                for (int p = 0; p < 2; p++) {
                    const int n = wn * 32 + p * 16 + (lane & 15);
                    LDMATRIX_X4(b[p][0], b[p][1], b[p][2], b[p][3],
                                Bb + n * RSTRIDE + ch * 16);
                }
                #pragma unroll
                for (int mt = 0; mt < 2; mt++)
                    #pragma unroll
                    for (int nt = 0; nt < 4; nt++) {
                        const int p = nt >> 1, sel = nt & 1;
                        mma_f16(acc[mt][nt][0], acc[mt][nt][1], acc[mt][nt][2], acc[mt][nt][3],
                                a[mt][0], a[mt][1], a[mt][2], a[mt][3],
                                b[p][sel], b[p][2 + sel]);
                    }
            }
            __syncthreads();
        }
    }

    // ---------- epilogue: out = dinv_i * (acc + z_i) + b ----------
    #pragma unroll
    for (int mt = 0; mt < 2; mt++) {
        const int r0 = wm * 32 + mt * 16 + gid;
        const int r1 = r0 + 8;
        const float di0 = g_dinv[m0 + r0];
        const float di1 = g_dinv[m0 + r1];
        #pragma unroll
        for (int nt = 0; nt < 4; nt++) {
            const int col = n0 + wn * 32 + nt * 8 + tig * 2;
            const float2 bb = *reinterpret_cast<const float2*>(bias + col);
            const float2 z0 = *reinterpret_cast<const float2*>(g_z + (size_t)(m0 + r0) * 128 + col);
            const float2 z1 = *reinterpret_cast<const float2*>(g_z + (size_t)(m0 + r1) * 128 + col);
            float2 o0, o1;
            o0.x = di0 * (acc[mt][nt][0] + z0.x) + bb.x;
            o0.y = di0 * (acc[mt][nt][1] + z0.y) + bb.y;
            o1.x = di1 * (acc[mt][nt][2] + z1.x) + bb.x;
            o1.y = di1 * (acc[mt][nt][3] + z1.y) + bb.y;
            *reinterpret_cast<float2*>(out + (size_t)(m0 + r0) * 128 + col) = o0;
            *reinterpret_cast<float2*>(out + (size_t)(m0 + r1) * 128 + col) = o1;
        }
    }
}

// ============================================================================
// launch
// ============================================================================
extern "C" void kernel_launch(void* const* d_in, const int* in_sizes, int n_in,
                              void* d_out, int out_size) {
    (void)in_sizes; (void)n_in; (void)out_size;
    const float* x   = (const float*)d_in[0];
    const float* adj = (const float*)d_in[1];
    const float* W   = (const float*)d_in[2];
    const float* b   = (const float*)d_in[3];
    float* out = (float*)d_out;

    void* caddr = nullptr;
    cudaGetSymbolAddress(&caddr, g_cnt);
    cudaMemsetAsync(caddr, 0, 8 * sizeof(int));
    kmain<<<NCTA, 256, SMEM_DYN>>>(x, adj, W, b, out);
}

// round 7
// speedup vs baseline: 1.7860x; 1.3132x over previous
#include <cuda_runtime.h>
#include <cuda_fp16.h>
#include <cstdint>
#include <cstddef>

#define NROWS 8192
#define CDIM  128

// ---------------- device scratch ----------------
__device__ float  g_dinv[NROWS];
__device__ __half g_zT_h[CDIM * NROWS];          // zT[c][j] fp16
__device__ float  g_z[NROWS * CDIM];             // z[j][c] fp32
__device__ float  g_part[4 * NROWS * CDIM];      // split-K partials

// ---------------- helpers ----------------
__device__ __forceinline__ uint32_t smem_u32(const void* p) {
    uint32_t a;
    asm("{ .reg .u64 t; cvta.to.shared.u64 t, %1; cvt.u32.u64 %0, t; }" : "=r"(a) : "l"(p));
    return a;
}
__device__ __forceinline__ uint32_t pack_f16x2(float x, float y) {
    uint32_t h;
    asm("cvt.rn.f16x2.f32 %0, %1, %2;" : "=r"(h) : "f"(y), "f"(x));
    return h;
}
#define CP_ASYNC16(dst, src) \
    asm volatile("cp.async.cg.shared.global [%0], [%1], 16;" :: "r"(dst), "l"(src) : "memory")
#define CP_COMMIT() asm volatile("cp.async.commit_group;" ::: "memory")
#define CP_WAIT0()  asm volatile("cp.async.wait_group 0;" ::: "memory")

#define LDMATRIX_X4(r0, r1, r2, r3, addr)                                    \
    asm volatile("ldmatrix.sync.aligned.m8n8.x4.shared.b16 {%0,%1,%2,%3}, [%4];" \
                 : "=r"(r0), "=r"(r1), "=r"(r2), "=r"(r3) : "r"(addr))

// fp16-accumulate MMA: D(2xu32) = A*B + C(2xu32)
__device__ __forceinline__ void mma_f16h(uint32_t& d0, uint32_t& d1,
                                         uint32_t a0, uint32_t a1, uint32_t a2, uint32_t a3,
                                         uint32_t b0, uint32_t b1) {
    asm volatile(
        "mma.sync.aligned.m16n8k16.row.col.f16.f16.f16.f16 "
        "{%0,%1}, {%2,%3,%4,%5}, {%6,%7}, {%0,%1};"
        : "+r"(d0), "+r"(d1)
        : "r"(a0), "r"(a1), "r"(a2), "r"(a3), "r"(b0), "r"(b1));
}

// ============================================================================
// K1: dinv[i] = rsqrt(1 + sum_j adj[i][j])
// ============================================================================
__global__ void __launch_bounds__(256) k1_rowsum(const float* __restrict__ adj) {
    const int row = blockIdx.x;
    const float4* p = reinterpret_cast<const float4*>(adj + (size_t)row * NROWS);
    float s = 0.0f;
    #pragma unroll 4
    for (int i = threadIdx.x; i < NROWS / 4; i += 256) {
        float4 v = p[i];
        s += (v.x + v.y) + (v.z + v.w);
    }
    #pragma unroll
    for (int o = 16; o > 0; o >>= 1) s += __shfl_xor_sync(0xFFFFFFFFu, s, o);
    __shared__ float ws[8];
    if ((threadIdx.x & 31) == 0) ws[threadIdx.x >> 5] = s;
    __syncthreads();
    if (threadIdx.x == 0) {
        float t = 0.0f;
        #pragma unroll
        for (int i = 0; i < 8; i++) t += ws[i];
        g_dinv[row] = rsqrtf(t + 1.0f);
    }
}

// ============================================================================
// K2: zT_h[c][j] = fp16(dinv_j * sum_k x[j][k]*W[c][k]);  z[j][c] fp32
// ============================================================================
__global__ void __launch_bounds__(128) k2_xw(const float* __restrict__ x,
                                             const float* __restrict__ W) {
    extern __shared__ float sh2[];
    float* Ws = sh2;                 // [128][132]
    float* xs = sh2 + 128 * 132;     // [16][128]
    const int c = threadIdx.x;
    const int j0 = blockIdx.x * 16;

    for (int idx = c; idx < 128 * 128; idx += 128)
        Ws[(idx >> 7) * 132 + (idx & 127)] = W[idx];
    for (int idx = c; idx < 16 * 128; idx += 128)
        xs[idx] = x[(size_t)(j0 + (idx >> 7)) * 128 + (idx & 127)];
    __syncthreads();

    float acc[16];
    #pragma unroll
    for (int r = 0; r < 16; r++) acc[r] = 0.0f;
    for (int k = 0; k < 128; k += 4) {
        float4 wv = *reinterpret_cast<const float4*>(&Ws[c * 132 + k]);
        #pragma unroll
        for (int r = 0; r < 16; r++) {
            float4 xv = *reinterpret_cast<const float4*>(&xs[r * 128 + k]);
            acc[r] += xv.x * wv.x + xv.y * wv.y + xv.z * wv.z + xv.w * wv.w;
        }
    }
    float v[16];
    #pragma unroll
    for (int r = 0; r < 16; r++) {
        v[r] = g_dinv[j0 + r] * acc[r];
        g_z[(size_t)(j0 + r) * 128 + c] = v[r];
    }
    #pragma unroll
    for (int m = 0; m < 2; m++) {
        uint4 q;
        q.x = pack_f16x2(v[8*m+0], v[8*m+1]);
        q.y = pack_f16x2(v[8*m+2], v[8*m+3]);
        q.z = pack_f16x2(v[8*m+4], v[8*m+5]);
        q.w = pack_f16x2(v[8*m+6], v[8*m+7]);
        *reinterpret_cast<uint4*>(&g_zT_h[(size_t)c * NROWS + j0 + 8 * m]) = q;
    }
}

// ============================================================================
// K3: split-K GEMM, fp16 mma with FP16 ACCUMULATE, promoted to fp32 every
// K=512 (4 kt iterations). Otherwise identical to the R4 127us kernel.
// ============================================================================
static constexpr int BK = 32;
static constexpr int RSTRIDE = 80;
static constexpr int TILE_B = 128 * RSTRIDE;
static constexpr int SMEM_K3 = 4 * TILE_B;         // 40960

__global__ void __launch_bounds__(256, 2) k3_gemm(const float* __restrict__ adj) {
    extern __shared__ char sm3[];
    const uint32_t base = smem_u32(sm3);
    const int tid = threadIdx.x;
    const int wid = tid >> 5, lane = tid & 31;
    const int gid = lane >> 2, tig = lane & 3;
    const int wm = wid & 3;
    const int wn = wid >> 2;

    const int tile = blockIdx.x & 63;
    const int ks = blockIdx.x >> 6;
    const int m0 = tile * 128;
    const int kbase = ks * 2048;
    const int NK = 2048 / BK;        // 64

    const uint32_t Ab0 = base, Ab1 = base + TILE_B;
    const uint32_t Bb0 = base + 2 * TILE_B, Bb1 = base + 3 * TILE_B;

    const int ar[4] = { (tid + 0) >> 3, (tid + 256) >> 3, (tid + 512) >> 3, (tid + 768) >> 3 };
    const int aqf = tid & 7;

    float4 pf[4];
    #define LDA(kt) do {                                                         \
        const int _k0 = kbase + (kt) * BK;                                       \
        _Pragma("unroll")                                                        \
        for (int i = 0; i < 4; i++)                                              \
            pf[i] = *reinterpret_cast<const float4*>(                            \
                adj + (size_t)(m0 + ar[i]) * NROWS + _k0 + aqf * 4);             \
    } while (0)

    #define STA(buf) do {                                                        \
        _Pragma("unroll")                                                        \
        for (int i = 0; i < 4; i++) {                                            \
            uint32_t h0 = pack_f16x2(pf[i].x, pf[i].y);                          \
            uint32_t h1 = pack_f16x2(pf[i].z, pf[i].w);                          \
            asm volatile("st.shared.v2.b32 [%0], {%1,%2};"                       \
                :: "r"((buf) + ar[i] * RSTRIDE + aqf * 8), "r"(h0), "r"(h1)      \
                : "memory");                                                     \
        }                                                                        \
    } while (0)

    #define CPB(kt, buf) do {                                                    \
        const int _k0 = kbase + (kt) * BK;                                       \
        _Pragma("unroll")                                                        \
        for (int i = 0; i < 2; i++) {                                            \
            const int id = tid + 256 * i;                                        \
            const int r = id >> 2, q = id & 3;                                   \
            CP_ASYNC16((buf) + r * RSTRIDE + q * 16,                             \
                       (const void*)(g_zT_h + (size_t)r * NROWS + _k0 + q * 8)); \
        }                                                                        \
    } while (0)

    // fp32 master accumulators + fp16 segment accumulators
    float acc[2][8][4];
    uint32_t acch[2][8][2];
    #pragma unroll
    for (int i = 0; i < 2; i++)
        #pragma unroll
        for (int j = 0; j < 8; j++) {
            #pragma unroll
            for (int t = 0; t < 4; t++) acc[i][j][t] = 0.0f;
            acch[i][j][0] = 0u; acch[i][j][1] = 0u;
        }

    LDA(0);
    CPB(0, Bb0); CP_COMMIT();

    for (int kt = 0; kt < NK; kt++) {
        const uint32_t Ab = (kt & 1) ? Ab1 : Ab0;
        const uint32_t Bb = (kt & 1) ? Bb1 : Bb0;
        STA(Ab);
        CP_WAIT0();
        __syncthreads();
        if (kt + 1 < NK) {
            LDA(kt + 1);
            CPB(kt + 1, (kt & 1) ? Bb0 : Bb1);
            CP_COMMIT();
        }
        // -------- mma (fp16 accum) --------
        #pragma unroll
        for (int s = 0; s < 2; s++) {
            const int ch = 2 * s + (lane >> 4);
            uint32_t a[2][4], b[4][4];
            #pragma unroll
            for (int mt = 0; mt < 2; mt++) {
                const int r = wm * 32 + mt * 16 + (lane & 15);
                LDMATRIX_X4(a[mt][0], a[mt][1], a[mt][2], a[mt][3],
                            Ab + r * RSTRIDE + ch * 16);
            }
            #pragma unroll
            for (int p = 0; p < 4; p++) {
                const int r = wn * 64 + p * 16 + (lane & 15);
                LDMATRIX_X4(b[p][0], b[p][1], b[p][2], b[p][3],
                            Bb + r * RSTRIDE + ch * 16);
            }
            #pragma unroll
            for (int mt = 0; mt < 2; mt++)
                #pragma unroll
                for (int nt = 0; nt < 8; nt++) {
                    const int p = nt >> 1, sel = nt & 1;
                    mma_f16h(acch[mt][nt][0], acch[mt][nt][1],
                             a[mt][0], a[mt][1], a[mt][2], a[mt][3],
                             b[p][sel], b[p][2 + sel]);
                }
        }
        // -------- promote fp16 segment -> fp32 every K=512 --------
        if ((kt & 3) == 3) {
            #pragma unroll
            for (int mt = 0; mt < 2; mt++)
                #pragma unroll
                for (int nt = 0; nt < 8; nt++) {
                    float2 lo = __half22float2(*reinterpret_cast<__half2*>(&acch[mt][nt][0]));
                    float2 hi = __half22float2(*reinterpret_cast<__half2*>(&acch[mt][nt][1]));
                    acc[mt][nt][0] += lo.x;
                    acc[mt][nt][1] += lo.y;
                    acc[mt][nt][2] += hi.x;
                    acc[mt][nt][3] += hi.y;
                    acch[mt][nt][0] = 0u;
                    acch[mt][nt][1] = 0u;
                }
        }
        __syncthreads();
    }

    // write partials
    float* part = g_part + (size_t)ks * (NROWS * CDIM) + (size_t)m0 * CDIM;
    #pragma unroll
    for (int mt = 0; mt < 2; mt++) {
        const int r0 = wm * 32 + mt * 16 + gid;
        #pragma unroll
        for (int nt = 0; nt < 8; nt++) {
            const int col = wn * 64 + nt * 8 + tig * 2;
            *reinterpret_cast<float2*>(part + (size_t)r0 * 128 + col) =
                make_float2(acc[mt][nt][0], acc[mt][nt][1]);
            *reinterpret_cast<float2*>(part + (size_t)(r0 + 8) * 128 + col) =
                make_float2(acc[mt][nt][2], acc[mt][nt][3]);
        }
    }
    #undef LDA
    #undef STA
    #undef CPB
}

// ============================================================================
// K4: out[i][c] = dinv_i * (sum_s part[s][i][c] + z[i][c]) + b[c]
// ============================================================================
__global__ void __launch_bounds__(256) k4_reduce(const float* __restrict__ bias,
                                                 float* __restrict__ out) {
    const int idx = blockIdx.x * 256 + threadIdx.x;
    const int i = idx >> 5;
    const int c4 = (idx & 31) * 4;
    const size_t off = (size_t)i * 128 + c4;

    float4 s = *reinterpret_cast<const float4*>(g_z + off);
    #pragma unroll
    for (int sp = 0; sp < 4; sp++) {
        float4 p = *reinterpret_cast<const float4*>(g_part + (size_t)sp * (NROWS * CDIM) + off);
        s.x += p.x; s.y += p.y; s.z += p.z; s.w += p.w;
    }
    const float di = g_dinv[i];
    const float4 bb = *reinterpret_cast<const float4*>(bias + c4);
    float4 o;
    o.x = di * s.x + bb.x;
    o.y = di * s.y + bb.y;
    o.z = di * s.z + bb.z;
    o.w = di * s.w + bb.w;
    *reinterpret_cast<float4*>(out + off) = o;
}

// ============================================================================
// launch
// ============================================================================
extern "C" void kernel_launch(void* const* d_in, const int* in_sizes, int n_in,
                              void* d_out, int out_size) {
    (void)in_sizes; (void)n_in; (void)out_size;
    const float* x   = (const float*)d_in[0];
    const float* adj = (const float*)d_in[1];
    const float* W   = (const float*)d_in[2];
    const float* b   = (const float*)d_in[3];
    float* out = (float*)d_out;

    const int smem_k2 = (128 * 132 + 16 * 128) * 4;
    cudaFuncSetAttribute(k2_xw, cudaFuncAttributeMaxDynamicSharedMemorySize, smem_k2);
    cudaFuncSetAttribute(k3_gemm, cudaFuncAttributeMaxDynamicSharedMemorySize, SMEM_K3);

    k1_rowsum<<<NROWS, 256>>>(adj);
    k2_xw<<<NROWS / 16, 128, smem_k2>>>(x, W);
    k3_gemm<<<256, 256, SMEM_K3>>>(adj);
    k4_reduce<<<NROWS * CDIM / 4 / 256, 256>>>(b, out);
}